// round 1
// baseline (speedup 1.0000x reference)
#include <cuda_runtime.h>
#include <cstdint>

// Problem constants
#define NN   100000   // nodes
#define RR   4        // relations
#define EE   500000   // edges per relation
#define INF  256
#define HIDF 128
#define OUTF 64

// ---------------------------------------------------------------------------
// Static device scratch (allocation-free per harness rules)
// ---------------------------------------------------------------------------
static __device__ float g_h[(size_t)NN * HIDF];      // per-relation transformed features (51.2 MB)
static __device__ float g_acc1[(size_t)NN * HIDF];   // layer-1 accumulator            (51.2 MB)
static __device__ float g_rs[2 * RR * NN];           // rsqrt degrees: [out | in]      (3.2 MB)

// ---------------------------------------------------------------------------
// f32x2 packed-FMA helpers (Blackwell sm_103a: 2x fp32 throughput vs FFMA)
// ---------------------------------------------------------------------------
__device__ __forceinline__ unsigned long long pack2(float x) {
    unsigned long long r;
    asm("mov.b64 %0, {%1, %1};" : "=l"(r) : "f"(x));
    return r;
}
__device__ __forceinline__ void fma2(unsigned long long& c,
                                     unsigned long long a,
                                     unsigned long long b) {
    asm("fma.rn.f32x2 %0, %1, %2, %0;" : "+l"(c) : "l"(a), "l"(b));
}
__device__ __forceinline__ void unpack2(unsigned long long c, float& lo, float& hi) {
    asm("mov.b64 {%0, %1}, %2;" : "=f"(lo), "=f"(hi) : "l"(c));
}

// ---------------------------------------------------------------------------
// Small utility kernels
// ---------------------------------------------------------------------------
__global__ void fzero_kernel(float* p, int n) {
    int i = blockIdx.x * blockDim.x + threadIdx.x;
    if (i < n) p[i] = 0.0f;
}

// Count out/in degrees for all relations in one pass.
__global__ void degree_count_kernel(const int* __restrict__ src,
                                    const int* __restrict__ dst,
                                    float* __restrict__ rs_out,
                                    float* __restrict__ rs_in) {
    int i = blockIdx.x * blockDim.x + threadIdx.x;
    if (i >= RR * EE) return;
    int r = i / EE;
    atomicAdd(&rs_out[r * NN + src[i]], 1.0f);
    atomicAdd(&rs_in [r * NN + dst[i]], 1.0f);
}

__global__ void degree_finalize_kernel(float* p, int n) {
    int i = blockIdx.x * blockDim.x + threadIdx.x;
    if (i < n) p[i] = rsqrtf(fmaxf(p[i], 1.0f));
}

// acc[i] = sum_r b[r][f]  (bias init; covers entire [N, F] buffer)
template <int F>
__global__ void init_bias_kernel(float* __restrict__ acc, const float* __restrict__ b) {
    int i = blockIdx.x * blockDim.x + threadIdx.x;
    if (i >= NN * F) return;
    int f = i % F;
    float s = b[0 * F + f] + b[1 * F + f] + b[2 * F + f] + b[3 * F + f];
    acc[i] = s;
}

// ---------------------------------------------------------------------------
// Row-scaled GEMM:  H[m, 0:BN] = (act(X[m, :]) * rs[m]) @ W[:, 0:BN]
// act = ReLU if RELU. BN is the full output width (128 or 64).
// BM=128, BK=16, 256 threads, TM=8 rows x TN cols per thread, f32x2 FMAs.
// ---------------------------------------------------------------------------
template <int BN, int TN, bool RELU>
__global__ __launch_bounds__(256, 2)
void gemm_scaled_kernel(const float* __restrict__ X,
                        const float* __restrict__ W,
                        const float* __restrict__ rs,
                        float* __restrict__ H,
                        int M, int K) {
    constexpr int BM = 128;
    constexpr int BK = 16;
    constexpr int TM = 8;
    constexpr int NTH = 256;

    __shared__ __align__(16) float As[BK][BM + 4];   // padded: conflict-free transposed stores
    __shared__ __align__(16) float Bs[BK][BN];

    const int t = threadIdx.x;
    const int rowBase = blockIdx.x * BM;

    const int tr = t / (BN / TN);   // 0..15
    const int tc = t % (BN / TN);   // 0..15
    const int r0 = tr * TM;
    const int c0 = tc * TN;

    unsigned long long acc[TM][TN / 2];
#pragma unroll
    for (int i = 0; i < TM; ++i)
#pragma unroll
        for (int j = 0; j < TN / 2; ++j) acc[i][j] = 0ull;

    for (int k0 = 0; k0 < K; k0 += BK) {
        // ---- load A tile (BM x BK), transposed into As[k][row], scaled ----
        constexpr int A4 = BM * BK / 4;   // 512 float4s
#pragma unroll
        for (int i = 0; i < A4 / NTH; ++i) {
            int id = t + i * NTH;
            int row = id / (BK / 4);
            int kk4 = id % (BK / 4);
            int grow = rowBase + row;
            float4 v = make_float4(0.f, 0.f, 0.f, 0.f);
            float sc = 0.f;
            if (grow < M) {
                v = *reinterpret_cast<const float4*>(X + (size_t)grow * K + k0 + kk4 * 4);
                sc = rs[grow];
            }
            if (RELU) {
                v.x = fmaxf(v.x, 0.f); v.y = fmaxf(v.y, 0.f);
                v.z = fmaxf(v.z, 0.f); v.w = fmaxf(v.w, 0.f);
            }
            v.x *= sc; v.y *= sc; v.z *= sc; v.w *= sc;
            As[kk4 * 4 + 0][row] = v.x;
            As[kk4 * 4 + 1][row] = v.y;
            As[kk4 * 4 + 2][row] = v.z;
            As[kk4 * 4 + 3][row] = v.w;
        }
        // ---- load B tile (BK x BN) ----
        constexpr int B4 = BK * BN / 4;
#pragma unroll
        for (int i = 0; i < (B4 + NTH - 1) / NTH; ++i) {
            int id = t + i * NTH;
            if ((B4 % NTH == 0) || (id < B4)) {
                int kk = id / (BN / 4);
                int c4 = id % (BN / 4);
                float4 v = *reinterpret_cast<const float4*>(W + (size_t)(k0 + kk) * BN + c4 * 4);
                *reinterpret_cast<float4*>(&Bs[kk][c4 * 4]) = v;
            }
        }
        __syncthreads();

        // ---- compute ----
#pragma unroll
        for (int kk = 0; kk < BK; ++kk) {
            float a[TM];
#pragma unroll
            for (int i = 0; i < TM; i += 4) {
                float4 av = *reinterpret_cast<const float4*>(&As[kk][r0 + i]);
                a[i] = av.x; a[i + 1] = av.y; a[i + 2] = av.z; a[i + 3] = av.w;
            }
            unsigned long long b[TN / 2];
#pragma unroll
            for (int j = 0; j < TN / 2; j += 2) {
                ulonglong2 bv = *reinterpret_cast<const ulonglong2*>(&Bs[kk][c0 + j * 2]);
                b[j] = bv.x; b[j + 1] = bv.y;
            }
#pragma unroll
            for (int i = 0; i < TM; ++i) {
                unsigned long long ad = pack2(a[i]);
#pragma unroll
                for (int j = 0; j < TN / 2; ++j) fma2(acc[i][j], ad, b[j]);
            }
        }
        __syncthreads();
    }

    // ---- epilogue ----
#pragma unroll
    for (int i = 0; i < TM; ++i) {
        int grow = rowBase + r0 + i;
        if (grow < M) {
            float* Hrow = H + (size_t)grow * BN + c0;
#pragma unroll
            for (int j = 0; j < TN / 2; ++j) {
                float lo, hi;
                unpack2(acc[i][j], lo, hi);
                reinterpret_cast<float2*>(Hrow)[j] = make_float2(lo, hi);
            }
        }
    }
}

// ---------------------------------------------------------------------------
// Edge scatter:  acc[dst, :] += rsqrt(deg_in[dst]) * H[src, :]
// Warp per edge -> atomics coalesce per 32B sector at L2.
// ---------------------------------------------------------------------------
template <int F>
__global__ void scatter_add_kernel(const float* __restrict__ H,
                                   const int* __restrict__ src,
                                   const int* __restrict__ dst,
                                   const float* __restrict__ rs_in,
                                   float* __restrict__ acc) {
    int gw = (blockIdx.x * blockDim.x + threadIdx.x) >> 5;
    int lane = threadIdx.x & 31;
    if (gw >= EE) return;
    int s = src[gw];
    int d = dst[gw];
    float c = __ldg(&rs_in[d]);
    const float* hrow = H + (size_t)s * F;
    float* arow = acc + (size_t)d * F;
#pragma unroll
    for (int i = 0; i < F / 32; ++i) {
        atomicAdd(arow + i * 32 + lane, c * __ldg(hrow + i * 32 + lane));
    }
}

// ---------------------------------------------------------------------------
// Launch
// ---------------------------------------------------------------------------
extern "C" void kernel_launch(void* const* d_in, const int* in_sizes, int n_in,
                              void* d_out, int out_size) {
    const float* x    = (const float*)d_in[0];
    const int*   esrc = (const int*)  d_in[1];
    const int*   edst = (const int*)  d_in[2];
    const float* W1   = (const float*)d_in[3];
    const float* b1   = (const float*)d_in[4];
    const float* W2   = (const float*)d_in[5];
    const float* b2   = (const float*)d_in[6];
    float* out = (float*)d_out;

    float *h, *acc1, *rs;
    cudaGetSymbolAddress((void**)&h,    g_h);
    cudaGetSymbolAddress((void**)&acc1, g_acc1);
    cudaGetSymbolAddress((void**)&rs,   g_rs);
    float* rs_out = rs;
    float* rs_in  = rs + RR * NN;

    const int TPB = 256;

    // Degrees (shared by both layers)
    {
        int n = 2 * RR * NN;
        fzero_kernel<<<(n + TPB - 1) / TPB, TPB>>>(rs, n);
        degree_count_kernel<<<(RR * EE + TPB - 1) / TPB, TPB>>>(esrc, edst, rs_out, rs_in);
        degree_finalize_kernel<<<(n + TPB - 1) / TPB, TPB>>>(rs, n);
    }

    const int gemmGrid    = (NN + 127) / 128;                 // 782
    const int scatterGrid = (EE * 32 + TPB - 1) / TPB;        // 62500

    // ---- Layer 1 ----
    init_bias_kernel<HIDF><<<(NN * HIDF + TPB - 1) / TPB, TPB>>>(acc1, b1);
    for (int r = 0; r < RR; ++r) {
        gemm_scaled_kernel<HIDF, 8, false><<<gemmGrid, TPB>>>(
            x, W1 + (size_t)r * INF * HIDF, rs_out + r * NN, h, NN, INF);
        scatter_add_kernel<HIDF><<<scatterGrid, TPB>>>(
            h, esrc + (size_t)r * EE, edst + (size_t)r * EE, rs_in + r * NN, acc1);
    }

    // ---- Layer 2 (ReLU fused into GEMM A-load) ----
    init_bias_kernel<OUTF><<<(NN * OUTF + TPB - 1) / TPB, TPB>>>(out, b2);
    for (int r = 0; r < RR; ++r) {
        gemm_scaled_kernel<OUTF, 4, true><<<gemmGrid, TPB>>>(
            acc1, W2 + (size_t)r * HIDF * OUTF, rs_out + r * NN, h, NN, HIDF);
        scatter_add_kernel<OUTF><<<scatterGrid, TPB>>>(
            h, esrc + (size_t)r * EE, edst + (size_t)r * EE, rs_in + r * NN, out);
    }
}